// round 14
// baseline (speedup 1.0000x reference)
#include <cuda_runtime.h>
#include <cuda_bf16.h>
#include <cstdint>

#define Bz 8
#define Nn 10000
#define Ee 160000
#define Hh 128
#define Zz 64

#define TROWS 128
#define NTILE ((Nn + TROWS - 1) / TROWS)   /* 79 */
#define SAF 68                              /* smem row stride in floats */

// ---------------- static device scratch ----------------
__device__ int    g_deg[Nn];
__device__ int    g_rowptr[Nn + 1];
__device__ int    g_cursor[Nn];
__device__ int    g_csr[Ee];
__device__ float2 g_ax[Bz * Nn];            // (layer-1 scalar mean, x) per (b,n)
__device__ float  g_S[(size_t)Bz * Nn * Hh];    // neighbor-mean h1 only (41 MB)
__device__ float  g_Wf[Hh * 256];           // W rows: [W2l | W2r] (128 KB)
__device__ float  g_pool[Bz * Hh];

// ---------------- PTX helpers (sm_80-compatible) ----------------
__device__ __forceinline__ uint32_t cvt_tf32(float f) {
    uint32_t r;
    asm("cvt.rna.tf32.f32 %0, %1;" : "=r"(r) : "f"(f));
    return r;
}
__device__ __forceinline__ void mma_tf32(float* d, const uint32_t* a, uint32_t b0, uint32_t b1) {
    asm volatile(
        "mma.sync.aligned.m16n8k8.row.col.f32.tf32.tf32.f32 "
        "{%0,%1,%2,%3}, {%4,%5,%6,%7}, {%8,%9}, {%0,%1,%2,%3};"
        : "+f"(d[0]), "+f"(d[1]), "+f"(d[2]), "+f"(d[3])
        : "r"(a[0]), "r"(a[1]), "r"(a[2]), "r"(a[3]), "r"(b0), "r"(b1));
}

// ---------------- helpers ----------------
__device__ __forceinline__ float4 relu_fma4(float4 wl, float4 wr, float4 bb, float a, float xv) {
    float4 o;
    o.x = fmaxf(fmaf(wl.x, a, fmaf(wr.x, xv, bb.x)), 0.f);
    o.y = fmaxf(fmaf(wl.y, a, fmaf(wr.y, xv, bb.y)), 0.f);
    o.z = fmaxf(fmaf(wl.z, a, fmaf(wr.z, xv, bb.z)), 0.f);
    o.w = fmaxf(fmaf(wl.w, a, fmaf(wr.w, xv, bb.w)), 0.f);
    return o;
}

// ---------------- prep kernels ----------------
__global__ void k_init() {
    int i = blockIdx.x * blockDim.x + threadIdx.x;
    if (i < Nn)      g_deg[i] = 0;
    if (i < Bz * Hh) g_pool[i] = 0.f;
}

__global__ void k_deg(const int* __restrict__ ei) {
    int e = blockIdx.x * blockDim.x + threadIdx.x;
    if (e >= Ee) return;
    atomicAdd(&g_deg[ei[Ee + e]], 1);
}

__global__ void k_scan() {
    __shared__ int sdata[1024];
    const int t = threadIdx.x;
    const int base = t * 10;
    int vals[10];
    int sum = 0;
#pragma unroll
    for (int i = 0; i < 10; i++) {
        int idx = base + i;
        int d = (idx < Nn) ? g_deg[idx] : 0;
        vals[i] = sum;
        sum += d;
    }
    sdata[t] = sum;
    __syncthreads();
    for (int off = 1; off < 1024; off <<= 1) {
        int v = (t >= off) ? sdata[t - off] : 0;
        __syncthreads();
        sdata[t] += v;
        __syncthreads();
    }
    int blockoff = (t > 0) ? sdata[t - 1] : 0;
#pragma unroll
    for (int i = 0; i < 10; i++) {
        int idx = base + i;
        if (idx < Nn) {
            int v = blockoff + vals[i];
            g_rowptr[idx] = v;
            g_cursor[idx] = v;
        }
    }
    if (t == 1023) g_rowptr[Nn] = sdata[1023];
}

__global__ void k_scatter(const int* __restrict__ ei) {
    int e = blockIdx.x * blockDim.x + threadIdx.x;
    if (e >= Ee) return;
    int s = ei[e];
    int d = ei[Ee + e];
    int pos = atomicAdd(&g_cursor[d], 1);
    g_csr[pos] = s;
}

__global__ void k_ax(const float* __restrict__ x) {
    int n = blockIdx.x * blockDim.x + threadIdx.x;
    int b = blockIdx.y;
    if (n >= Nn) return;
    int beg = g_rowptr[n], end = g_rowptr[n + 1];
    float s = 0.f;
    for (int e = beg; e < end; e++) s += __ldg(&x[b * Nn + g_csr[e]]);
    float a = s / fmaxf((float)(end - beg), 1.f);
    g_ax[b * Nn + n] = make_float2(a, __ldg(&x[b * Nn + n]));
}

// W rows: Wf[n][k] = k<128 ? W2l[n][k] : W2r[n][k-128]
__global__ void k_wb(const float* __restrict__ W2l, const float* __restrict__ W2r) {
    int i = blockIdx.x * blockDim.x + threadIdx.x;
    if (i >= Hh * 256) return;
    int n = i >> 8;
    int k = i & 255;
    g_Wf[i] = (k < Hh) ? __ldg(&W2l[n * Hh + k]) : __ldg(&W2r[n * Hh + (k - Hh)]);
}

// warp per (b,node): S[b,n,:] = mean_j relu(h1_j)   (neighbor-mean half only)
__global__ void k_agg2(const float* __restrict__ W1l, const float* __restrict__ b1,
                       const float* __restrict__ W1r) {
    int unit = (blockIdx.x * blockDim.x + threadIdx.x) >> 5;
    int lane = threadIdx.x & 31;
    if (unit >= Bz * Nn) return;
    int b = unit / Nn;
    int n = unit - b * Nn;

    const float4 wl = __ldg(((const float4*)W1l) + lane);
    const float4 wr = __ldg(((const float4*)W1r) + lane);
    const float4 bb = __ldg(((const float4*)b1) + lane);
    const float2* axb = g_ax + b * Nn;

    int beg = g_rowptr[n], end = g_rowptr[n + 1];
    float4 agg = make_float4(0.f, 0.f, 0.f, 0.f);
    for (int e = beg; e < end; e++) {
        int s = g_csr[e];                 // warp-uniform
        float2 axj = axb[s];              // 8B broadcast
        float4 h = relu_fma4(wl, wr, bb, axj.x, axj.y);
        agg.x += h.x; agg.y += h.y; agg.z += h.z; agg.w += h.w;
    }
    float inv = 1.f / fmaxf((float)(end - beg), 1.f);
    agg.x *= inv; agg.y *= inv; agg.z *= inv; agg.w *= inv;

    *(float4*)(g_S + (size_t)unit * Hh + 4 * lane) = agg;
}

// ---------------- tf32 tensor-core GEMM + pooled epilogue ----------------
// SMEM tiles store each 8-k group INTERLEAVED [k0,k0+4,k1,k1+5,k2,k2+6,k3,k3+7]
// so mma fragment pairs (k, k+4) are contiguous -> LDS.64 in the hot loop.
// K chunks 0-1: A = g_S. K chunks 2-3: A = self-h1 computed from cached ax tile.
#define SMEM_A_OFF 0
#define SMEM_B_OFF (128 * SAF * 4)
#define SMEM_POOL  (2 * 128 * SAF * 4)
#define SMEM_AXS   (SMEM_POOL + 128 * 4)
#define SMEM_TOT   (SMEM_AXS + 128 * 8)

__global__ void __launch_bounds__(256) k_mma(
    const float* __restrict__ b2, const float* __restrict__ W1l,
    const float* __restrict__ b1, const float* __restrict__ W1r)
{
    extern __shared__ char dsm[];
    float*  sA   = (float*)(dsm + SMEM_A_OFF);
    float*  sB   = (float*)(dsm + SMEM_B_OFF);
    float*  pool = (float*)(dsm + SMEM_POOL);
    float2* axs  = (float2*)(dsm + SMEM_AXS);

    const int t = threadIdx.x;
    const int lane = t & 31;
    const int warp = t >> 5;
    const int wm = warp >> 1;      // 0..3 : rows wm*32..+32
    const int wn = warp & 1;       // 0..1 : cols wn*64..+64
    const int b = blockIdx.y;
    const int row0 = blockIdx.x * TROWS;

    if (t < 128) {
        pool[t] = 0.f;
        int gr = row0 + t;
        axs[t] = (gr < Nn) ? g_ax[b * Nn + gr] : make_float2(0.f, 0.f);
    }

    const int gf  = t & 7;    // k-group within chunk (fill), constant per thread
    const int rf0 = t >> 3;   // base fill row

    float acc[2][8][4];
#pragma unroll
    for (int i = 0; i < 2; i++)
#pragma unroll
        for (int j = 0; j < 8; j++)
#pragma unroll
            for (int q = 0; q < 4; q++) acc[i][j][q] = 0.f;

    __syncthreads();

    for (int c = 0; c < 4; c++) {
        // ---- fill A chunk (64 k x 128 rows), interleaved pairs ----
        if (c < 2) {
#pragma unroll
            for (int it = 0; it < 4; it++) {
                int r = it * 32 + rf0;        // 0..127
                int grow = row0 + r;
                float4 lo = make_float4(0.f, 0.f, 0.f, 0.f);
                float4 hi = lo;
                if (grow < Nn) {
                    const float* src = g_S + ((size_t)(b * Nn + grow)) * Hh + c * 64 + gf * 8;
                    lo = *(const float4*)(src);
                    hi = *(const float4*)(src + 4);
                }
                float* dst = sA + r * SAF + gf * 8;
                *(float2*)(dst + 0) = make_float2(lo.x, hi.x);
                *(float2*)(dst + 2) = make_float2(lo.y, hi.y);
                *(float2*)(dst + 4) = make_float2(lo.z, hi.z);
                *(float2*)(dst + 6) = make_float2(lo.w, hi.w);
            }
        } else {
            int hq = (c - 2) * 16 + gf * 2;   // float4 index into W1 (k = hq*4)
            float4 wl0 = __ldg(((const float4*)W1l) + hq);
            float4 wr0 = __ldg(((const float4*)W1r) + hq);
            float4 bb0 = __ldg(((const float4*)b1) + hq);
            float4 wl1 = __ldg(((const float4*)W1l) + hq + 1);
            float4 wr1 = __ldg(((const float4*)W1r) + hq + 1);
            float4 bb1 = __ldg(((const float4*)b1) + hq + 1);
#pragma unroll
            for (int it = 0; it < 4; it++) {
                int r = it * 32 + rf0;
                float2 ax = axs[r];
                float4 lo = relu_fma4(wl0, wr0, bb0, ax.x, ax.y);
                float4 hi = relu_fma4(wl1, wr1, bb1, ax.x, ax.y);
                float* dst = sA + r * SAF + gf * 8;
                *(float2*)(dst + 0) = make_float2(lo.x, hi.x);
                *(float2*)(dst + 2) = make_float2(lo.y, hi.y);
                *(float2*)(dst + 4) = make_float2(lo.z, hi.z);
                *(float2*)(dst + 6) = make_float2(lo.w, hi.w);
            }
        }
        // ---- fill B chunk (64 k x 128 n), interleaved pairs ----
#pragma unroll
        for (int it = 0; it < 4; it++) {
            int r = it * 32 + rf0;            // n row 0..127
            const float* src = g_Wf + (size_t)r * 256 + c * 64 + gf * 8;
            float4 lo = *(const float4*)(src);
            float4 hi = *(const float4*)(src + 4);
            float* dst = sB + r * SAF + gf * 8;
            *(float2*)(dst + 0) = make_float2(lo.x, hi.x);
            *(float2*)(dst + 2) = make_float2(lo.y, hi.y);
            *(float2*)(dst + 4) = make_float2(lo.z, hi.z);
            *(float2*)(dst + 6) = make_float2(lo.w, hi.w);
        }
        __syncthreads();

        // ---- 8 k-steps of 8: paired LDS.64 ----
#pragma unroll
        for (int ks = 0; ks < 8; ks++) {
            const int k0 = ks * 8 + 2 * (lane & 3);   // interleaved position of (k, k+4)
            uint32_t afr[2][4];
#pragma unroll
            for (int mt = 0; mt < 2; mt++) {
                const float* Ar = sA + (wm * 32 + mt * 16 + (lane >> 2)) * SAF + k0;
                float2 p0 = *(const float2*)(Ar);             // row m:   (k, k+4)
                float2 p1 = *(const float2*)(Ar + 8 * SAF);   // row m+8: (k, k+4)
                afr[mt][0] = cvt_tf32(p0.x);
                afr[mt][1] = cvt_tf32(p1.x);
                afr[mt][2] = cvt_tf32(p0.y);
                afr[mt][3] = cvt_tf32(p1.y);
            }
#pragma unroll
            for (int nb = 0; nb < 8; nb++) {
                const float* Br = sB + (wn * 64 + nb * 8 + (lane >> 2)) * SAF + k0;
                float2 pb = *(const float2*)(Br);
                uint32_t b0 = cvt_tf32(pb.x);
                uint32_t b1v = cvt_tf32(pb.y);
                mma_tf32(acc[0][nb], afr[0], b0, b1v);
                mma_tf32(acc[1][nb], afr[1], b0, b1v);
            }
        }
        __syncthreads();
    }

    // ---- epilogue: bias + relu + row-mask + column sums ----
#pragma unroll
    for (int nt = 0; nt < 8; nt++) {
        int c0 = wn * 64 + nt * 8 + (lane & 3) * 2;
        float bb0 = __ldg(&b2[c0]);
        float bb1 = __ldg(&b2[c0 + 1]);
        float v0 = 0.f, v1 = 0.f;
#pragma unroll
        for (int mt = 0; mt < 2; mt++) {
            int grow = row0 + wm * 32 + mt * 16 + (lane >> 2);
            if (grow < Nn) {
                v0 += fmaxf(acc[mt][nt][0] + bb0, 0.f);
                v1 += fmaxf(acc[mt][nt][1] + bb1, 0.f);
            }
            if (grow + 8 < Nn) {
                v0 += fmaxf(acc[mt][nt][2] + bb0, 0.f);
                v1 += fmaxf(acc[mt][nt][3] + bb1, 0.f);
            }
        }
        v0 += __shfl_xor_sync(0xFFFFFFFFu, v0, 4);
        v1 += __shfl_xor_sync(0xFFFFFFFFu, v1, 4);
        v0 += __shfl_xor_sync(0xFFFFFFFFu, v0, 8);
        v1 += __shfl_xor_sync(0xFFFFFFFFu, v1, 8);
        v0 += __shfl_xor_sync(0xFFFFFFFFu, v0, 16);
        v1 += __shfl_xor_sync(0xFFFFFFFFu, v1, 16);
        if (lane < 4) {
            atomicAdd(&pool[c0], v0);
            atomicAdd(&pool[c0 + 1], v1);
        }
    }
    __syncthreads();
    if (t < 128) atomicAdd(&g_pool[b * Hh + t], pool[t]);
}

// ---------------- final MLP ----------------
__global__ void k_final(float* __restrict__ out,
                        const float* __restrict__ Wro1, const float* __restrict__ bro1,
                        const float* __restrict__ Wro2, const float* __restrict__ bro2) {
    __shared__ float pl[Bz][Hh];
    __shared__ float hid[Bz][Hh];
    int t = threadIdx.x;  // 128
    const float invn = 1.f / (float)Nn;
#pragma unroll
    for (int b = 0; b < Bz; b++) pl[b][t] = g_pool[b * Hh + t] * invn;
    __syncthreads();
#pragma unroll
    for (int b = 0; b < Bz; b++) {
        float s0 = __ldg(&bro1[t]), s1 = 0.f, s2 = 0.f, s3 = 0.f;
        for (int h = 0; h < Hh; h += 4) {
            s0 = fmaf(pl[b][h + 0], __ldg(&Wro1[t * Hh + h + 0]), s0);
            s1 = fmaf(pl[b][h + 1], __ldg(&Wro1[t * Hh + h + 1]), s1);
            s2 = fmaf(pl[b][h + 2], __ldg(&Wro1[t * Hh + h + 2]), s2);
            s3 = fmaf(pl[b][h + 3], __ldg(&Wro1[t * Hh + h + 3]), s3);
        }
        hid[b][t] = fmaxf((s0 + s1) + (s2 + s3), 0.f);
    }
    __syncthreads();
    if (t < Zz) {
#pragma unroll
        for (int b = 0; b < Bz; b++) {
            float s0 = __ldg(&bro2[t]), s1 = 0.f, s2 = 0.f, s3 = 0.f;
            for (int h = 0; h < Hh; h += 4) {
                s0 = fmaf(hid[b][h + 0], __ldg(&Wro2[t * Hh + h + 0]), s0);
                s1 = fmaf(hid[b][h + 1], __ldg(&Wro2[t * Hh + h + 1]), s1);
                s2 = fmaf(hid[b][h + 2], __ldg(&Wro2[t * Hh + h + 2]), s2);
                s3 = fmaf(hid[b][h + 3], __ldg(&Wro2[t * Hh + h + 3]), s3);
            }
            out[b * Zz + t] = (s0 + s1) + (s2 + s3);
        }
    }
}

// ---------------- launcher ----------------
extern "C" void kernel_launch(void* const* d_in, const int* in_sizes, int n_in,
                              void* d_out, int out_size) {
    const float* x    = (const float*)d_in[0];
    const int*   ei   = (const int*)d_in[1];     // int32 (JAX x64 disabled)
    const float* W1l  = (const float*)d_in[2];
    const float* b1   = (const float*)d_in[3];
    const float* W1r  = (const float*)d_in[4];
    const float* W2l  = (const float*)d_in[5];
    const float* b2   = (const float*)d_in[6];
    const float* W2r  = (const float*)d_in[7];
    const float* Wro1 = (const float*)d_in[8];
    const float* bro1 = (const float*)d_in[9];
    const float* Wro2 = (const float*)d_in[10];
    const float* bro2 = (const float*)d_in[11];
    float* out = (float*)d_out;

    cudaFuncSetAttribute(k_mma, cudaFuncAttributeMaxDynamicSharedMemorySize, SMEM_TOT);

    k_init<<<(Nn + 255) / 256, 256>>>();
    k_deg<<<(Ee + 255) / 256, 256>>>(ei);
    k_scan<<<1, 1024>>>();
    k_scatter<<<(Ee + 255) / 256, 256>>>(ei);
    k_ax<<<dim3((Nn + 255) / 256, Bz), 256>>>(x);
    k_wb<<<(Hh * 256 + 255) / 256, 256>>>(W2l, W2r);
    k_agg2<<<(Bz * Nn * 32 + 255) / 256, 256>>>(W1l, b1, W1r);
    k_mma<<<dim3(NTILE, Bz), 256, SMEM_TOT>>>(b2, W1l, b1, W1r);
    k_final<<<1, 128>>>(out, Wro1, bro1, Wro2, bro2);
}

// round 15
// speedup vs baseline: 1.8699x; 1.8699x over previous
#include <cuda_runtime.h>
#include <cuda_bf16.h>
#include <cstdint>

#define Bz 8
#define Nn 10000
#define Ee 160000
#define Hh 128
#define Zz 64

#define TROWS 128
#define NTILE ((Nn + TROWS - 1) / TROWS)   /* 79 */
#define SAF 68                              /* smem row stride in floats */

// ---------------- static device scratch ----------------
__device__ int    g_deg[Nn];
__device__ int    g_rowptr[Nn + 1];
__device__ int    g_cursor[Nn];
__device__ int    g_csr[Ee];
__device__ float2 g_ax[Bz * Nn];            // (layer-1 scalar mean, x) per (b,n)
__device__ float  g_S[(size_t)Bz * Nn * Hh];    // neighbor-mean h1 only (41 MB)
__device__ float  g_Wf[Hh * 256];           // W rows: [W2l | W2r] (128 KB)
__device__ float  g_pool[Bz * Hh];

// ---------------- PTX helpers (sm_80-compatible) ----------------
__device__ __forceinline__ uint32_t cvt_tf32(float f) {
    uint32_t r;
    asm("cvt.rna.tf32.f32 %0, %1;" : "=r"(r) : "f"(f));
    return r;
}
__device__ __forceinline__ void mma_tf32(float* d, const uint32_t* a, uint32_t b0, uint32_t b1) {
    asm volatile(
        "mma.sync.aligned.m16n8k8.row.col.f32.tf32.tf32.f32 "
        "{%0,%1,%2,%3}, {%4,%5,%6,%7}, {%8,%9}, {%0,%1,%2,%3};"
        : "+f"(d[0]), "+f"(d[1]), "+f"(d[2]), "+f"(d[3])
        : "r"(a[0]), "r"(a[1]), "r"(a[2]), "r"(a[3]), "r"(b0), "r"(b1));
}

// ---------------- helpers ----------------
__device__ __forceinline__ float4 relu_fma4(float4 wl, float4 wr, float4 bb, float a, float xv) {
    float4 o;
    o.x = fmaxf(fmaf(wl.x, a, fmaf(wr.x, xv, bb.x)), 0.f);
    o.y = fmaxf(fmaf(wl.y, a, fmaf(wr.y, xv, bb.y)), 0.f);
    o.z = fmaxf(fmaf(wl.z, a, fmaf(wr.z, xv, bb.z)), 0.f);
    o.w = fmaxf(fmaf(wl.w, a, fmaf(wr.w, xv, bb.w)), 0.f);
    return o;
}

// ---------------- prep kernels ----------------
__global__ void k_init() {
    int i = blockIdx.x * blockDim.x + threadIdx.x;
    if (i < Nn)      g_deg[i] = 0;
    if (i < Bz * Hh) g_pool[i] = 0.f;
}

__global__ void k_deg(const int* __restrict__ ei) {
    int e = blockIdx.x * blockDim.x + threadIdx.x;
    if (e >= Ee) return;
    atomicAdd(&g_deg[ei[Ee + e]], 1);
}

__global__ void k_scan() {
    __shared__ int sdata[1024];
    const int t = threadIdx.x;
    const int base = t * 10;
    int vals[10];
    int sum = 0;
#pragma unroll
    for (int i = 0; i < 10; i++) {
        int idx = base + i;
        int d = (idx < Nn) ? g_deg[idx] : 0;
        vals[i] = sum;
        sum += d;
    }
    sdata[t] = sum;
    __syncthreads();
    for (int off = 1; off < 1024; off <<= 1) {
        int v = (t >= off) ? sdata[t - off] : 0;
        __syncthreads();
        sdata[t] += v;
        __syncthreads();
    }
    int blockoff = (t > 0) ? sdata[t - 1] : 0;
#pragma unroll
    for (int i = 0; i < 10; i++) {
        int idx = base + i;
        if (idx < Nn) {
            int v = blockoff + vals[i];
            g_rowptr[idx] = v;
            g_cursor[idx] = v;
        }
    }
    if (t == 1023) g_rowptr[Nn] = sdata[1023];
}

__global__ void k_scatter(const int* __restrict__ ei) {
    int e = blockIdx.x * blockDim.x + threadIdx.x;
    if (e >= Ee) return;
    int s = ei[e];
    int d = ei[Ee + e];
    int pos = atomicAdd(&g_cursor[d], 1);
    g_csr[pos] = s;
}

__global__ void k_ax(const float* __restrict__ x) {
    int n = blockIdx.x * blockDim.x + threadIdx.x;
    int b = blockIdx.y;
    if (n >= Nn) return;
    int beg = g_rowptr[n], end = g_rowptr[n + 1];
    float s = 0.f;
    for (int e = beg; e < end; e++) s += __ldg(&x[b * Nn + g_csr[e]]);
    float a = s / fmaxf((float)(end - beg), 1.f);
    g_ax[b * Nn + n] = make_float2(a, __ldg(&x[b * Nn + n]));
}

// W rows: Wf[n][k] = k<128 ? W2l[n][k] : W2r[n][k-128]
__global__ void k_wb(const float* __restrict__ W2l, const float* __restrict__ W2r) {
    int i = blockIdx.x * blockDim.x + threadIdx.x;
    if (i >= Hh * 256) return;
    int n = i >> 8;
    int k = i & 255;
    g_Wf[i] = (k < Hh) ? __ldg(&W2l[n * Hh + k]) : __ldg(&W2r[n * Hh + (k - Hh)]);
}

// warp per (b,node): S[b,n,:] = mean_j relu(h1_j), with 1-deep (csr,ax) prefetch
__global__ void k_agg2(const float* __restrict__ W1l, const float* __restrict__ b1,
                       const float* __restrict__ W1r) {
    int unit = (blockIdx.x * blockDim.x + threadIdx.x) >> 5;
    int lane = threadIdx.x & 31;
    if (unit >= Bz * Nn) return;
    int b = unit / Nn;
    int n = unit - b * Nn;

    const float4 wl = __ldg(((const float4*)W1l) + lane);
    const float4 wr = __ldg(((const float4*)W1r) + lane);
    const float4 bb = __ldg(((const float4*)b1) + lane);
    const float2* axb = g_ax + b * Nn;

    int beg = g_rowptr[n], end = g_rowptr[n + 1];
    float4 agg = make_float4(0.f, 0.f, 0.f, 0.f);

    float2 nx = make_float2(0.f, 0.f);
    if (beg < end) nx = axb[g_csr[beg]];
    for (int e = beg; e < end; e++) {
        float2 cur = nx;
        if (e + 1 < end) nx = axb[g_csr[e + 1]];   // prefetch next; overlaps FMAs below
        float4 h = relu_fma4(wl, wr, bb, cur.x, cur.y);
        agg.x += h.x; agg.y += h.y; agg.z += h.z; agg.w += h.w;
    }
    float inv = 1.f / fmaxf((float)(end - beg), 1.f);
    agg.x *= inv; agg.y *= inv; agg.z *= inv; agg.w *= inv;

    *(float4*)(g_S + (size_t)unit * Hh + 4 * lane) = agg;
}

// ---------------- tf32 tensor-core GEMM + pooled epilogue ----------------
// (byte-identical to champion R9/R13 — local optimum, do not touch)
#define SMEM_A_OFF 0
#define SMEM_B_OFF (128 * SAF * 4)
#define SMEM_POOL  (2 * 128 * SAF * 4)
#define SMEM_AXS   (SMEM_POOL + 128 * 4)
#define SMEM_TOT   (SMEM_AXS + 128 * 8)

__global__ void __launch_bounds__(256) k_mma(
    const float* __restrict__ b2, const float* __restrict__ W1l,
    const float* __restrict__ b1, const float* __restrict__ W1r)
{
    extern __shared__ char dsm[];
    float*  sA   = (float*)(dsm + SMEM_A_OFF);
    float*  sB   = (float*)(dsm + SMEM_B_OFF);
    float*  pool = (float*)(dsm + SMEM_POOL);
    float2* axs  = (float2*)(dsm + SMEM_AXS);

    const int t = threadIdx.x;
    const int lane = t & 31;
    const int warp = t >> 5;
    const int wm = warp >> 1;      // 0..3 : rows wm*32..+32
    const int wn = warp & 1;       // 0..1 : cols wn*64..+64
    const int b = blockIdx.y;
    const int row0 = blockIdx.x * TROWS;

    if (t < 128) {
        pool[t] = 0.f;
        int gr = row0 + t;
        axs[t] = (gr < Nn) ? g_ax[b * Nn + gr] : make_float2(0.f, 0.f);
    }

    const int u = t & 15;

    float acc[2][8][4];
#pragma unroll
    for (int i = 0; i < 2; i++)
#pragma unroll
        for (int j = 0; j < 8; j++)
#pragma unroll
            for (int q = 0; q < 4; q++) acc[i][j][q] = 0.f;

    __syncthreads();

    for (int c = 0; c < 4; c++) {
        // ---- fill A chunk (64 k x 128 rows) ----
        if (c < 2) {
#pragma unroll
            for (int it = 0; it < 8; it++) {
                int idx = it * 256 + t;       // 0..2047
                int r = idx >> 4;             // 0..127
                int grow = row0 + r;
                float4 va = make_float4(0.f, 0.f, 0.f, 0.f);
                if (grow < Nn)
                    va = *(const float4*)(g_S + ((size_t)(b * Nn + grow)) * Hh + c * 64 + u * 4);
                *(float4*)(sA + r * SAF + u * 4) = va;
            }
        } else {
            int hq = (c - 2) * 16 + u;        // float4 index into W1 (h = hq*4)
            float4 wl = __ldg(((const float4*)W1l) + hq);
            float4 wr = __ldg(((const float4*)W1r) + hq);
            float4 bb = __ldg(((const float4*)b1) + hq);
#pragma unroll
            for (int it = 0; it < 8; it++) {
                int idx = it * 256 + t;
                int r = idx >> 4;
                float2 ax = axs[r];
                *(float4*)(sA + r * SAF + u * 4) = relu_fma4(wl, wr, bb, ax.x, ax.y);
            }
        }
        // ---- load B chunk (64 k x 128 n) ----
#pragma unroll
        for (int it = 0; it < 8; it++) {
            int idx = it * 256 + t;
            int r = idx >> 4;
            *(float4*)(sB + r * SAF + u * 4) =
                *(const float4*)(g_Wf + (size_t)r * 256 + c * 64 + u * 4);
        }
        __syncthreads();

        // ---- 8 k-steps of 8 ----
#pragma unroll
        for (int ks = 0; ks < 8; ks++) {
            const int k0 = ks * 8 + (lane & 3);
            uint32_t afr[2][4];
#pragma unroll
            for (int mt = 0; mt < 2; mt++) {
                const float* Ar = sA + (wm * 32 + mt * 16 + (lane >> 2)) * SAF + k0;
                afr[mt][0] = cvt_tf32(Ar[0]);
                afr[mt][1] = cvt_tf32(Ar[8 * SAF]);
                afr[mt][2] = cvt_tf32(Ar[4]);
                afr[mt][3] = cvt_tf32(Ar[8 * SAF + 4]);
            }
#pragma unroll
            for (int nb = 0; nb < 8; nb++) {
                const float* Br = sB + (wn * 64 + nb * 8 + (lane >> 2)) * SAF + k0;
                uint32_t b0 = cvt_tf32(Br[0]);
                uint32_t b1v = cvt_tf32(Br[4]);
                mma_tf32(acc[0][nb], afr[0], b0, b1v);
                mma_tf32(acc[1][nb], afr[1], b0, b1v);
            }
        }
        __syncthreads();
    }

    // ---- epilogue: bias + relu + row-mask + column sums ----
#pragma unroll
    for (int nt = 0; nt < 8; nt++) {
        int c0 = wn * 64 + nt * 8 + (lane & 3) * 2;
        float bb0 = __ldg(&b2[c0]);
        float bb1 = __ldg(&b2[c0 + 1]);
        float v0 = 0.f, v1 = 0.f;
#pragma unroll
        for (int mt = 0; mt < 2; mt++) {
            int grow = row0 + wm * 32 + mt * 16 + (lane >> 2);
            if (grow < Nn) {
                v0 += fmaxf(acc[mt][nt][0] + bb0, 0.f);
                v1 += fmaxf(acc[mt][nt][1] + bb1, 0.f);
            }
            if (grow + 8 < Nn) {
                v0 += fmaxf(acc[mt][nt][2] + bb0, 0.f);
                v1 += fmaxf(acc[mt][nt][3] + bb1, 0.f);
            }
        }
        v0 += __shfl_xor_sync(0xFFFFFFFFu, v0, 4);
        v1 += __shfl_xor_sync(0xFFFFFFFFu, v1, 4);
        v0 += __shfl_xor_sync(0xFFFFFFFFu, v0, 8);
        v1 += __shfl_xor_sync(0xFFFFFFFFu, v1, 8);
        v0 += __shfl_xor_sync(0xFFFFFFFFu, v0, 16);
        v1 += __shfl_xor_sync(0xFFFFFFFFu, v1, 16);
        if (lane < 4) {
            atomicAdd(&pool[c0], v0);
            atomicAdd(&pool[c0 + 1], v1);
        }
    }
    __syncthreads();
    if (t < 128) atomicAdd(&g_pool[b * Hh + t], pool[t]);
}

// ---------------- final MLP: one block per batch ----------------
__global__ void k_final(float* __restrict__ out,
                        const float* __restrict__ Wro1, const float* __restrict__ bro1,
                        const float* __restrict__ Wro2, const float* __restrict__ bro2) {
    __shared__ float pl[Hh];
    __shared__ float hid[Hh];
    const int b = blockIdx.x;
    const int t = threadIdx.x;  // 128
    const float invn = 1.f / (float)Nn;

    pl[t] = g_pool[b * Hh + t] * invn;
    __syncthreads();

    {
        float s0 = __ldg(&bro1[t]), s1 = 0.f, s2 = 0.f, s3 = 0.f;
        for (int h = 0; h < Hh; h += 4) {
            s0 = fmaf(pl[h + 0], __ldg(&Wro1[t * Hh + h + 0]), s0);
            s1 = fmaf(pl[h + 1], __ldg(&Wro1[t * Hh + h + 1]), s1);
            s2 = fmaf(pl[h + 2], __ldg(&Wro1[t * Hh + h + 2]), s2);
            s3 = fmaf(pl[h + 3], __ldg(&Wro1[t * Hh + h + 3]), s3);
        }
        hid[t] = fmaxf((s0 + s1) + (s2 + s3), 0.f);
    }
    __syncthreads();
    if (t < Zz) {
        float s0 = __ldg(&bro2[t]), s1 = 0.f, s2 = 0.f, s3 = 0.f;
        for (int h = 0; h < Hh; h += 4) {
            s0 = fmaf(hid[h + 0], __ldg(&Wro2[t * Hh + h + 0]), s0);
            s1 = fmaf(hid[h + 1], __ldg(&Wro2[t * Hh + h + 1]), s1);
            s2 = fmaf(hid[h + 2], __ldg(&Wro2[t * Hh + h + 2]), s2);
            s3 = fmaf(hid[h + 3], __ldg(&Wro2[t * Hh + h + 3]), s3);
        }
        out[b * Zz + t] = (s0 + s1) + (s2 + s3);
    }
}

// ---------------- launcher ----------------
extern "C" void kernel_launch(void* const* d_in, const int* in_sizes, int n_in,
                              void* d_out, int out_size) {
    const float* x    = (const float*)d_in[0];
    const int*   ei   = (const int*)d_in[1];     // int32 (JAX x64 disabled)
    const float* W1l  = (const float*)d_in[2];
    const float* b1   = (const float*)d_in[3];
    const float* W1r  = (const float*)d_in[4];
    const float* W2l  = (const float*)d_in[5];
    const float* b2   = (const float*)d_in[6];
    const float* W2r  = (const float*)d_in[7];
    const float* Wro1 = (const float*)d_in[8];
    const float* bro1 = (const float*)d_in[9];
    const float* Wro2 = (const float*)d_in[10];
    const float* bro2 = (const float*)d_in[11];
    float* out = (float*)d_out;

    cudaFuncSetAttribute(k_mma, cudaFuncAttributeMaxDynamicSharedMemorySize, SMEM_TOT);

    k_init<<<(Nn + 255) / 256, 256>>>();
    k_deg<<<(Ee + 255) / 256, 256>>>(ei);
    k_scan<<<1, 1024>>>();
    k_scatter<<<(Ee + 255) / 256, 256>>>(ei);
    k_ax<<<dim3((Nn + 255) / 256, Bz), 256>>>(x);
    k_wb<<<(Hh * 256 + 255) / 256, 256>>>(W2l, W2r);
    k_agg2<<<(Bz * Nn * 32 + 255) / 256, 256>>>(W1l, b1, W1r);
    k_mma<<<dim3(NTILE, Bz), 256, SMEM_TOT>>>(b2, W1l, b1, W1r);
    k_final<<<Bz, 128>>>(out, Wro1, bro1, Wro2, bro2);
}